// round 16
// baseline (speedup 1.0000x reference)
#include <cuda_runtime.h>

#define BB 8
#define CC 256
#define HH 96
#define WW 96
#define HW (HH*WW)          // 9216
#define PATCH 21
#define NP    (PATCH*PATCH) // 441
#define HALFP 10
#define DILP 2
#define TROW 136            // 96 + 2*20 halo

#define NDOT  576           // dot units: 128 spatial floats x 256ch each
#define NPROD 288           // producer blocks (byte-identical R8 path)
#define NCONS 304           // consumer blocks
#define GRID  (NPROD + NCONS)   // 592 = 148*4, all resident at occ 4

// Consumer units (y-span gather, write-locality layout):
//  units [0,252):   batches 0..5, (b,py,yh) span=48  -> 18KB contiguous/chunk
//  units [252,420): batches 6..7, (b,py,yq) span=24  -> fine tail granularity
#define NUNIT   420
#define NCOARSE 252
#define NDBL    116         // blocks 0..115 take a second unit (304+cid)

__device__ float g_D[BB * HW];     // 1.18 MB, L2-resident
__device__ int   g_cnt[BB];        // per-batch completed dot units (target 72)
__device__ int   g_done;           // finished consumer blocks (self-reset)

// One y-span gather unit: stage SPAN consecutive D rows (halo-padded) into
// smem, then write 21 contiguous (SPAN*96-float) output chunks.
template <int SPAN>
__device__ __forceinline__ void do_gather(float* tile, int b, int py, int y0,
                                          int tid, float* __restrict__ out) {
    // zero tile (halo + OOB rows stay zero) while (possibly) waiting
    for (int i = tid; i < SPAN * TROW; i += 256) tile[i] = 0.f;

    if (tid == 0) {
        volatile int* c = &g_cnt[b];
        while (*c < 72) __nanosleep(100);
        __threadfence();                   // acquire
    }
    __syncthreads();

    // stage SPAN consecutive source rows: sy = y0 + yr + (py-10)*2
    const float4* __restrict__ D4 = (const float4*)g_D;
    const int syBase = y0 + (py - HALFP) * DILP;
    for (int i = tid; i < SPAN * 24; i += 256) {
        const int rr = i / 24;
        const int x4 = i - rr * 24;
        const int sy = syBase + rr;
        if ((unsigned)sy < (unsigned)HH) {
            float4 v = D4[(b * HH + sy) * 24 + x4];
            *(float4*)(tile + rr * TROW + 20 + x4 * 4) = v;
        }
    }
    __syncthreads();

    // emit: 21 px * SPAN rows * 24 float4. For fixed px the SPAN*96 floats
    // are CONTIGUOUS in gmem (y-major) -> DRAM row-friendly streaming.
    float4* __restrict__ O4 = (float4*)out;
    const size_t pbase = (size_t)b * NP + py * PATCH;
    for (int i = tid; i < PATCH * SPAN * 24; i += 256) {
        const int x4 = i % 24;
        const int t  = i / 24;
        const int yr = t % SPAN;
        const int px = t / SPAN;

        const float2* sp =
            (const float2*)(tile + yr * TROW + px * 2 + x4 * 4);
        float2 lo = sp[0];
        float2 hi = sp[1];

        O4[(pbase + px) * (HW / 4) + (size_t)(y0 + yr) * 24 + x4] =
            make_float4(lo.x, lo.y, hi.x, hi.y);
    }
    __syncthreads();                       // tile reuse safety
}

__device__ __forceinline__ void run_unit(int u, float* tile, int tid,
                                         float* __restrict__ out) {
    if (u < NCOARSE) {                     // batches 0..5, span 48
        const int b  = u / 42;
        const int r  = u - b * 42;
        do_gather<48>(tile, b, r >> 1, (r & 1) * 48, tid, out);
    } else {                               // batches 6..7, span 24
        const int v  = u - NCOARSE;
        const int b  = 6 + v / 84;
        const int r  = v % 84;
        do_gather<24>(tile, b, r >> 2, (r & 3) * 24, tid, out);
    }
}

__global__ void __launch_bounds__(256, 4) fused_kernel(
        const float* __restrict__ a,
        const float* __restrict__ b,
        float* __restrict__ out) {
    __shared__ union {
        float4 red[256];
        float  tile[48 * TROW];      // 26112 B (max span)
    } sm;

    const int tid = threadIdx.x;
    const int bid = blockIdx.x;

    if (bid < NPROD) {
        // ============ PRODUCER: dot units (byte-identical to R8) ===========
        const int lane = tid & 31;
        const int cg   = tid >> 5;
        const int cstride = HW / 4;
        const int c0 = cg * 32;

        for (int u = bid; u < NDOT; u += NPROD) {
            const int sbase = u * 128;
            const int bidx  = u / 72;                  // batch
            const int hw    = (sbase % HW) + lane * 4;

            const float4* __restrict__ A =
                (const float4*)(a + (size_t)bidx * CC * HW + hw);
            const float4* __restrict__ Bp =
                (const float4*)(b + (size_t)bidx * CC * HW + hw);

            float4 acc = make_float4(0.f, 0.f, 0.f, 0.f);
            #pragma unroll 4
            for (int c = 0; c < 32; ++c) {
                const size_t off = (size_t)(c0 + c) * cstride;
                float4 x = A[off];
                float4 y = Bp[off];
                acc.x = fmaf(x.x, y.x, acc.x);
                acc.y = fmaf(x.y, y.y, acc.y);
                acc.z = fmaf(x.z, y.z, acc.z);
                acc.w = fmaf(x.w, y.w, acc.w);
            }

            sm.red[tid] = acc;
            __syncthreads();
            if (tid < 32) {
                float4 r = sm.red[tid];
                #pragma unroll
                for (int k = 1; k < 8; ++k) {
                    float4 t = sm.red[tid + 32 * k];
                    r.x += t.x; r.y += t.y; r.z += t.z; r.w += t.w;
                }
                ((float4*)g_D)[(size_t)u * 32 + tid] = r;
            }
            __syncthreads();                       // reduce done, smem free
            if (tid == 0) {
                __threadfence();                   // publish g_D
                atomicAdd(&g_cnt[bidx], 1);
            }
        }
    } else {
        // ===== CONSUMER: y-span gather units, hybrid granularity ===========
        // block cid takes unit cid; blocks 0..115 also take unit 304+cid
        // (first unit = early batch, second = b6/b7 fine unit -> pipeline).
        const int cid = bid - NPROD;

        run_unit(cid, sm.tile, tid, out);
        if (cid < NDBL)
            run_unit(NCONS + cid, sm.tile, tid, out);

        // ---- self-clean: last consumer block resets sync state for the
        // next graph replay (proven in R6/R8).
        if (tid == 0) {
            __threadfence();
            int d = atomicAdd(&g_done, 1);
            if (d == NCONS - 1) {
                #pragma unroll
                for (int i = 0; i < BB; ++i) g_cnt[i] = 0;
                g_done = 0;
                __threadfence();
            }
        }
    }
}

extern "C" void kernel_launch(void* const* d_in, const int* in_sizes, int n_in,
                              void* d_out, int out_size) {
    const float* in1 = (const float*)d_in[0];
    const float* in2 = (const float*)d_in[1];
    float* out = (float*)d_out;

    fused_kernel<<<GRID, 256>>>(in1, in2, out);
}